// round 2
// baseline (speedup 1.0000x reference)
#include <cuda_runtime.h>
#include <math_constants.h>

#define NN 100000
#define EE 600000

// ---------------- scratch (device globals: no allocs allowed) ----------------
__device__ float g_q[NN * 128];
__device__ float g_k[NN * 128];
__device__ float g_v[NN * 128];
__device__ float g_e[(size_t)EE * 128];   // per-edge lin_edge output (307 MB)
__device__ float g_alpha[EE * 2];
__device__ float g_ex[EE * 2];
__device__ float g_amax[NN * 2];
__device__ float g_denom[NN * 2];

__device__ __forceinline__ void atomicMaxF(float* addr, float value) {
    if (value >= 0.f)
        atomicMax((int*)addr, __float_as_int(value));
    else
        atomicMin((unsigned int*)addr, (unsigned int)__float_as_int(value));
}

// ---------------- kernel 0: init segment buffers ----------------
__global__ void init_kernel() {
    int i = blockIdx.x * blockDim.x + threadIdx.x;
    if (i < NN * 2) {
        g_amax[i] = -CUDART_INF_F;
        g_denom[i] = 0.f;
    }
}

// ---------------- kernel 1: node projections (q,k,v,skip) ----------------
// grid (ceil(N/64), 4), 256 threads. blockIdx.y picks which projection.
// smem: W[128][128] (64KB) + x tile [64][132] (33KB)
#define NODE_SMEM ((16384 + 64 * 132) * 4)
__global__ void node_gemm_kernel(const float* __restrict__ x,
                                 const float* __restrict__ Wq, const float* __restrict__ bq,
                                 const float* __restrict__ Wk, const float* __restrict__ bk,
                                 const float* __restrict__ Wv, const float* __restrict__ bv,
                                 const float* __restrict__ Wsk, const float* __restrict__ bsk,
                                 float* __restrict__ out_skip)
{
    extern __shared__ float sm[];
    float* Ws = sm;             // 128*128
    float* xs = sm + 16384;     // 64 rows * stride 132

    const int tid = threadIdx.x;
    const float* W; const float* bias; float* dst;
    switch (blockIdx.y) {
        case 0:  W = Wq;  bias = bq;  dst = g_q;      break;
        case 1:  W = Wk;  bias = bk;  dst = g_k;      break;
        case 2:  W = Wv;  bias = bv;  dst = g_v;      break;
        default: W = Wsk; bias = bsk; dst = out_skip; break;
    }

    {
        const float4* W4 = (const float4*)W;
        float4* Ws4 = (float4*)Ws;
        #pragma unroll
        for (int i = 0; i < 16; i++) Ws4[i * 256 + tid] = W4[i * 256 + tid];
    }
    const int row0 = blockIdx.x * 64;
    {
        #pragma unroll
        for (int i = 0; i < 8; i++) {
            int idx = i * 256 + tid;
            int r = idx >> 5;
            int c4 = idx & 31;
            float4 v = make_float4(0.f, 0.f, 0.f, 0.f);
            if (row0 + r < NN) v = ((const float4*)x)[(row0 + r) * 32 + c4];
            *(float4*)(xs + r * 132 + c4 * 4) = v;
        }
    }
    __syncthreads();

    const int tx = tid & 15;
    const int ty = tid >> 4;
    const int c0 = tx * 8;
    const int r0 = ty * 4;

    float acc[4][8];
    #pragma unroll
    for (int i = 0; i < 4; i++)
        #pragma unroll
        for (int j = 0; j < 8; j++) acc[i][j] = 0.f;

    #pragma unroll 4
    for (int k = 0; k < 128; k++) {
        float4 b0 = *(const float4*)(Ws + k * 128 + c0);
        float4 b1 = *(const float4*)(Ws + k * 128 + c0 + 4);
        #pragma unroll
        for (int i = 0; i < 4; i++) {
            float a = xs[(r0 + i) * 132 + k];
            acc[i][0] += a * b0.x; acc[i][1] += a * b0.y;
            acc[i][2] += a * b0.z; acc[i][3] += a * b0.w;
            acc[i][4] += a * b1.x; acc[i][5] += a * b1.y;
            acc[i][6] += a * b1.z; acc[i][7] += a * b1.w;
        }
    }

    float bb[8];
    #pragma unroll
    for (int j = 0; j < 8; j++) bb[j] = __ldg(bias + c0 + j);

    #pragma unroll
    for (int i = 0; i < 4; i++) {
        int r = row0 + r0 + i;
        if (r < NN) {
            float4 o0 = make_float4(acc[i][0] + bb[0], acc[i][1] + bb[1],
                                    acc[i][2] + bb[2], acc[i][3] + bb[3]);
            float4 o1 = make_float4(acc[i][4] + bb[4], acc[i][5] + bb[5],
                                    acc[i][6] + bb[6], acc[i][7] + bb[7]);
            *(float4*)(dst + r * 128 + c0)     = o0;
            *(float4*)(dst + r * 128 + c0 + 4) = o1;
        }
    }
}

// ---------------- kernel 2: edge GEMM (lin_edge) + attention logits ----------------
// grid (E/64), 256 threads. builds edge_attr tile (time enc + msg) in smem,
// GEMMs against We, stores e, computes alpha = q_i . (k_j + e) / 8 fused.
#define EDGE_SMEM ((16384 + 64 * 132 + 64 * 16 + 64 * 3) * 4 + 64 * 2 * 4)
__global__ void edge_kernel(const float* __restrict__ last_update,
                            const int* __restrict__ eidx,
                            const float* __restrict__ t,
                            const float* __restrict__ msg,
                            const float* __restrict__ wt,
                            const float* __restrict__ bt,
                            const float* __restrict__ We)
{
    extern __shared__ float sm[];
    float* Ws    = sm;                 // 16384
    float* as    = sm + 16384;         // 64 * 132
    float* ps    = as + 64 * 132;      // 64 * 16 alpha partials
    float* relts = ps + 64 * 16;       // 64
    float* wts   = relts + 64;         // 64
    float* bts   = wts + 64;           // 64
    int*   srcs  = (int*)(bts + 64);   // 64
    int*   dsts  = srcs + 64;          // 64

    const int tid = threadIdx.x;
    const int e0 = blockIdx.x * 64;

    {
        const float4* W4 = (const float4*)We;
        float4* Ws4 = (float4*)Ws;
        #pragma unroll
        for (int i = 0; i < 16; i++) Ws4[i * 256 + tid] = W4[i * 256 + tid];
    }
    if (tid < 64) {
        wts[tid] = wt[tid];
        bts[tid] = bt[tid];
    } else if (tid < 128) {
        int r = tid - 64;
        int e = e0 + r;
        int s = eidx[e];
        srcs[r] = s;
        dsts[r] = eidx[EE + e];
        relts[r] = last_update[s] - t[e];
    }
    __syncthreads();

    // build edge_attr tile: cols 0..63 = cos(rel_t*wt+bt), cols 64..127 = msg
    #pragma unroll
    for (int i = 0; i < 8; i++) {
        int idx = i * 256 + tid;
        int r = idx >> 5;
        int c4 = idx & 31;
        if (c4 < 16) {
            int c = c4 * 4;
            float rt_ = relts[r];
            float4 v;
            v.x = cosf(fmaf(rt_, wts[c + 0], bts[c + 0]));
            v.y = cosf(fmaf(rt_, wts[c + 1], bts[c + 1]));
            v.z = cosf(fmaf(rt_, wts[c + 2], bts[c + 2]));
            v.w = cosf(fmaf(rt_, wts[c + 3], bts[c + 3]));
            *(float4*)(as + r * 132 + c) = v;
        } else {
            int c4m = c4 - 16;
            float4 v = ((const float4*)msg)[(e0 + r) * 16 + c4m];
            *(float4*)(as + r * 132 + 64 + c4m * 4) = v;
        }
    }
    __syncthreads();

    const int tx = tid & 15;
    const int ty = tid >> 4;
    const int c0 = tx * 8;
    const int r0 = ty * 4;

    float acc[4][8];
    #pragma unroll
    for (int i = 0; i < 4; i++)
        #pragma unroll
        for (int j = 0; j < 8; j++) acc[i][j] = 0.f;

    #pragma unroll 4
    for (int k = 0; k < 128; k++) {
        float4 b0 = *(const float4*)(Ws + k * 128 + c0);
        float4 b1 = *(const float4*)(Ws + k * 128 + c0 + 4);
        #pragma unroll
        for (int i = 0; i < 4; i++) {
            float a = as[(r0 + i) * 132 + k];
            acc[i][0] += a * b0.x; acc[i][1] += a * b0.y;
            acc[i][2] += a * b0.z; acc[i][3] += a * b0.w;
            acc[i][4] += a * b1.x; acc[i][5] += a * b1.y;
            acc[i][6] += a * b1.z; acc[i][7] += a * b1.w;
        }
    }

    // store e tile, compute alpha partials (thread covers 8 cols of one head)
    #pragma unroll
    for (int i = 0; i < 4; i++) {
        int r = r0 + i;
        int e = e0 + r;
        int s = srcs[r];
        int d = dsts[r];
        float4 q0 = *(const float4*)(g_q + (size_t)d * 128 + c0);
        float4 q1 = *(const float4*)(g_q + (size_t)d * 128 + c0 + 4);
        float4 k0 = *(const float4*)(g_k + (size_t)s * 128 + c0);
        float4 k1 = *(const float4*)(g_k + (size_t)s * 128 + c0 + 4);
        float part =
            q0.x * (k0.x + acc[i][0]) + q0.y * (k0.y + acc[i][1]) +
            q0.z * (k0.z + acc[i][2]) + q0.w * (k0.w + acc[i][3]) +
            q1.x * (k1.x + acc[i][4]) + q1.y * (k1.y + acc[i][5]) +
            q1.z * (k1.z + acc[i][6]) + q1.w * (k1.w + acc[i][7]);
        ps[r * 16 + tx] = part;
        float* ep = g_e + (size_t)e * 128 + c0;
        *(float4*)(ep)     = make_float4(acc[i][0], acc[i][1], acc[i][2], acc[i][3]);
        *(float4*)(ep + 4) = make_float4(acc[i][4], acc[i][5], acc[i][6], acc[i][7]);
    }
    __syncthreads();

    if (tid < 128) {
        int r = tid >> 1;
        int h = tid & 1;
        const float* p = ps + r * 16 + h * 8;
        float s_ = ((p[0] + p[1]) + (p[2] + p[3])) + ((p[4] + p[5]) + (p[6] + p[7]));
        g_alpha[(e0 + r) * 2 + h] = s_ * 0.125f;  // 1/sqrt(64)
    }
}

// ---------------- kernel 3: segment max ----------------
__global__ void amax_kernel(const int* __restrict__ eidx) {
    int i = blockIdx.x * blockDim.x + threadIdx.x;
    if (i >= EE * 2) return;
    int e = i >> 1;
    int h = i & 1;
    int d = eidx[EE + e];
    atomicMaxF(&g_amax[d * 2 + h], g_alpha[i]);
}

// ---------------- kernel 4: exp + segment sum ----------------
__global__ void ex_kernel(const int* __restrict__ eidx) {
    int i = blockIdx.x * blockDim.x + threadIdx.x;
    if (i >= EE * 2) return;
    int e = i >> 1;
    int h = i & 1;
    int d = eidx[EE + e];
    float ex = expf(g_alpha[i] - g_amax[d * 2 + h]);
    g_ex[i] = ex;
    atomicAdd(&g_denom[d * 2 + h], ex);
}

// ---------------- kernel 5: weighted scatter-add aggregation ----------------
__global__ void agg_kernel(const int* __restrict__ eidx, float* __restrict__ out) {
    long i = (long)blockIdx.x * blockDim.x + threadIdx.x;
    if (i >= (long)EE * 32) return;
    int e  = (int)(i >> 5);
    int c4 = (int)(i & 31);
    int c  = c4 * 4;
    int h  = c4 >> 4;
    int s = eidx[e];
    int d = eidx[EE + e];
    float attn = g_ex[e * 2 + h] / (g_denom[d * 2 + h] + 1e-16f);
    float4 vv = *(const float4*)(g_v + (size_t)s * 128 + c);
    float4 ev = *(const float4*)(g_e + (size_t)e * 128 + c);
    float x0 = attn * (vv.x + ev.x);
    float x1 = attn * (vv.y + ev.y);
    float x2 = attn * (vv.z + ev.z);
    float x3 = attn * (vv.w + ev.w);
    float* p = out + (size_t)d * 128 + c;
    asm volatile("red.global.add.v4.f32 [%0], {%1, %2, %3, %4};"
                 :: "l"(p), "f"(x0), "f"(x1), "f"(x2), "f"(x3) : "memory");
}

// ---------------- launch ----------------
extern "C" void kernel_launch(void* const* d_in, const int* in_sizes, int n_in,
                              void* d_out, int out_size) {
    const float* x    = (const float*)d_in[0];
    const float* lu   = (const float*)d_in[1];
    const int*   eidx = (const int*)d_in[2];
    const float* t    = (const float*)d_in[3];
    const float* msg  = (const float*)d_in[4];
    const float* wt   = (const float*)d_in[5];
    const float* bt   = (const float*)d_in[6];
    const float* Wq   = (const float*)d_in[7];
    const float* bq   = (const float*)d_in[8];
    const float* Wk   = (const float*)d_in[9];
    const float* bk   = (const float*)d_in[10];
    const float* Wv   = (const float*)d_in[11];
    const float* bv   = (const float*)d_in[12];
    const float* We   = (const float*)d_in[13];
    const float* Wsk  = (const float*)d_in[14];
    const float* bsk  = (const float*)d_in[15];
    float* out = (float*)d_out;

    cudaFuncSetAttribute(node_gemm_kernel, cudaFuncAttributeMaxDynamicSharedMemorySize, NODE_SMEM);
    cudaFuncSetAttribute(edge_kernel,      cudaFuncAttributeMaxDynamicSharedMemorySize, EDGE_SMEM);

    init_kernel<<<(NN * 2 + 255) / 256, 256>>>();
    node_gemm_kernel<<<dim3((NN + 63) / 64, 4), 256, NODE_SMEM>>>(
        x, Wq, bq, Wk, bk, Wv, bv, Wsk, bsk, out);
    edge_kernel<<<EE / 64, 256, EDGE_SMEM>>>(lu, eidx, t, msg, wt, bt, We);
    amax_kernel<<<(EE * 2 + 255) / 256, 256>>>(eidx);
    ex_kernel<<<(EE * 2 + 255) / 256, 256>>>(eidx);
    agg_kernel<<<(int)(((long)EE * 32 + 255) / 256), 256>>>(eidx, out);
}